// round 7
// baseline (speedup 1.0000x reference)
#include <cuda_runtime.h>
#include <cuda_bf16.h>
#include <cstdint>

#define N_NODES 100000
#define HEADS 8
#define OUT_CH 16
#define DIM 128            // IN_CH == OUT_DIM == 128
#define NEG_SLOPE 0.2f
#define LN_EPS 1e-5f

// ---------------- scratch (device globals; no allocation allowed) ----------
__device__ float    g_h   [(size_t)N_NODES * DIM];   // x @ W            51.2 MB
__device__ float    g_agg [(size_t)N_NODES * DIM];   // unnorm. message  51.2 MB
__device__ float    g_as  [N_NODES * HEADS];         // <h, att_src>
__device__ float    g_ad  [N_NODES * HEADS];         // <h, att_dst>
__device__ unsigned g_m   [N_NODES * HEADS];         // segment max (ordered-uint enc)
__device__ float    g_den [N_NODES * HEADS];         // softmax denom (unnorm)

// ---------------- helpers ---------------------------------------------------
__device__ __forceinline__ unsigned enc_f32(float f) {
    unsigned u = __float_as_uint(f);
    return (u & 0x80000000u) ? ~u : (u | 0x80000000u);
}
__device__ __forceinline__ float dec_f32(unsigned e) {
    return (e & 0x80000000u) ? __uint_as_float(e ^ 0x80000000u)
                             : __uint_as_float(~e);
}
__device__ __forceinline__ float leaky(float v) { return v > 0.f ? v : NEG_SLOPE * v; }

// ---------------- K1: h = x @ W  (128x128 block tile, 8x8 per thread) -------
#define GBM 128
#define GBK 16
__global__ __launch_bounds__(256) void k_gemm(const float* __restrict__ x,
                                              const float* __restrict__ W, int N) {
    __shared__ __align__(16) float As[GBK][GBM + 4];
    __shared__ __align__(16) float Bs[GBK][DIM];
    const int tid = threadIdx.x;
    const int row0 = blockIdx.x * GBM;
    const int tx = tid & 15, ty = tid >> 4;
    const int tm0 = ty * 8, tn0 = tx * 8;
    float acc[8][8] = {};

    for (int k0 = 0; k0 < DIM; k0 += GBK) {
#pragma unroll
        for (int i = 0; i < 2; i++) {
            int idx = tid * 2 + i;          // 0..511
            int r = idx >> 2, c4 = idx & 3;
            int gr = row0 + r;
            float4 v = make_float4(0.f, 0.f, 0.f, 0.f);
            if (gr < N) v = *(const float4*)&x[(size_t)gr * DIM + k0 + c4 * 4];
            As[c4 * 4 + 0][r] = v.x;
            As[c4 * 4 + 1][r] = v.y;
            As[c4 * 4 + 2][r] = v.z;
            As[c4 * 4 + 3][r] = v.w;
        }
#pragma unroll
        for (int i = 0; i < 2; i++) {
            int idx = tid * 2 + i;
            int r = idx >> 5, c4 = idx & 31;
            *(float4*)&Bs[r][c4 * 4] = *(const float4*)&W[(size_t)(k0 + r) * DIM + c4 * 4];
        }
        __syncthreads();
#pragma unroll
        for (int k = 0; k < GBK; k++) {
            float a[8], b[8];
            *(float4*)&a[0] = *(float4*)&As[k][tm0];
            *(float4*)&a[4] = *(float4*)&As[k][tm0 + 4];
            *(float4*)&b[0] = *(float4*)&Bs[k][tn0];
            *(float4*)&b[4] = *(float4*)&Bs[k][tn0 + 4];
#pragma unroll
            for (int i = 0; i < 8; i++)
#pragma unroll
                for (int j = 0; j < 8; j++) acc[i][j] += a[i] * b[j];
        }
        __syncthreads();
    }
#pragma unroll
    for (int i = 0; i < 8; i++) {
        int gr = row0 + tm0 + i;
        if (gr < N) {
            *(float4*)&g_h[(size_t)gr * DIM + tn0]     = *(float4*)&acc[i][0];
            *(float4*)&g_h[(size_t)gr * DIM + tn0 + 4] = *(float4*)&acc[i][4];
        }
    }
}

// ---------------- K2: per-node attention coefficients (warp per node) -------
__global__ __launch_bounds__(256) void k_asd(const float* __restrict__ att_s,
                                             const float* __restrict__ att_d, int N) {
    int w = (blockIdx.x * blockDim.x + threadIdx.x) >> 5;
    int lane = threadIdx.x & 31;
    if (w >= N) return;
    float4 hv = *(const float4*)&g_h[(size_t)w * DIM + lane * 4];
    float4 a = *(const float4*)&att_s[lane * 4];
    float4 b = *(const float4*)&att_d[lane * 4];
    float ps = hv.x * a.x + hv.y * a.y + hv.z * a.z + hv.w * a.w;
    float pd = hv.x * b.x + hv.y * b.y + hv.z * b.z + hv.w * b.w;
    ps += __shfl_xor_sync(0xffffffffu, ps, 1);
    ps += __shfl_xor_sync(0xffffffffu, ps, 2);
    pd += __shfl_xor_sync(0xffffffffu, pd, 1);
    pd += __shfl_xor_sync(0xffffffffu, pd, 2);
    if ((lane & 3) == 0) {
        g_as[w * HEADS + (lane >> 2)] = ps;
        g_ad[w * HEADS + (lane >> 2)] = pd;
    }
}

// ---------------- K3: init agg=0, den=0, m = self-loop logit ----------------
__global__ __launch_bounds__(256) void k_init(int N) {
    int tid = blockIdx.x * blockDim.x + threadIdx.x;
    if (tid < N * DIM) g_agg[tid] = 0.f;
    if (tid < N * HEADS) {
        g_den[tid] = 0.f;
        g_m[tid] = enc_f32(leaky(g_as[tid] + g_ad[tid]));
    }
}

// ---------------- K4: edge segment max (8 threads per edge) -----------------
__global__ __launch_bounds__(256) void k_max(const int* __restrict__ ei, int E) {
    int tid = blockIdx.x * blockDim.x + threadIdx.x;
    if (tid >= E * HEADS) return;
    int e = tid >> 3, hd = tid & 7;
    int src = ei[e];
    int dst = ei[E + e];
    float v = leaky(g_as[src * HEADS + hd] + g_ad[dst * HEADS + hd]);
    atomicMax(&g_m[dst * HEADS + hd], enc_f32(v));
}

// ---------------- K5: edge accumulate (warp per edge) -----------------------
__global__ __launch_bounds__(256) void k_acc(const int* __restrict__ ei, int E) {
    int w = (blockIdx.x * blockDim.x + threadIdx.x) >> 5;
    int lane = threadIdx.x & 31;
    if (w >= E) return;
    int src = 0, dst = 0;
    if (lane == 0) {
        src = ei[w];
        dst = ei[E + w];
    }
    src = __shfl_sync(0xffffffffu, src, 0);
    dst = __shfl_sync(0xffffffffu, dst, 0);

    float ex = 0.f;
    if (lane < HEADS) {
        float v = leaky(g_as[src * HEADS + lane] + g_ad[dst * HEADS + lane]);
        ex = __expf(v - dec_f32(g_m[dst * HEADS + lane]));
        atomicAdd(&g_den[dst * HEADS + lane], ex);
    }
    // lane handles channels [4*lane, 4*lane+4) -> head = lane/4
    float exh = __shfl_sync(0xffffffffu, ex, lane >> 2);
    float4 hv = *(const float4*)&g_h[(size_t)src * DIM + lane * 4];
    float* dp = &g_agg[(size_t)dst * DIM + lane * 4];
    atomicAdd(dp + 0, exh * hv.x);
    atomicAdd(dp + 1, exh * hv.y);
    atomicAdd(dp + 2, exh * hv.z);
    atomicAdd(dp + 3, exh * hv.w);
}

// ---------------- K6: self-loop + normalize + bias + LN + ELU ---------------
__global__ __launch_bounds__(128) void k_final(const float* __restrict__ bias,
                                               const float* __restrict__ gamma,
                                               const float* __restrict__ beta,
                                               float* __restrict__ out, int N) {
    int i = blockIdx.x;
    int ch = threadIdx.x;          // 0..127
    int hd = ch >> 4;
    float as = g_as[i * HEADS + hd], ad = g_ad[i * HEADS + hd];
    float es = leaky(as + ad);
    float mm = dec_f32(g_m[i * HEADS + hd]);
    float exs = __expf(es - mm);                       // self-loop weight
    float den = g_den[i * HEADS + hd] + exs;
    float val = (g_agg[(size_t)i * DIM + ch] + exs * g_h[(size_t)i * DIM + ch]) / den;
    val += bias[ch];

    // block LayerNorm over 128 channels
    __shared__ float ssum[4], ssq[4];
    float s = val, q = val * val;
#pragma unroll
    for (int o = 16; o > 0; o >>= 1) {
        s += __shfl_xor_sync(0xffffffffu, s, o);
        q += __shfl_xor_sync(0xffffffffu, q, o);
    }
    if ((ch & 31) == 0) { ssum[ch >> 5] = s; ssq[ch >> 5] = q; }
    __syncthreads();
    float S = ssum[0] + ssum[1] + ssum[2] + ssum[3];
    float Q = ssq[0] + ssq[1] + ssq[2] + ssq[3];
    float mu = S * (1.f / DIM);
    float var = Q * (1.f / DIM) - mu * mu;
    float y = (val - mu) * rsqrtf(var + LN_EPS) * gamma[ch] + beta[ch];
    out[(size_t)i * DIM + ch] = y > 0.f ? y : (__expf(y) - 1.f);
}

// ---------------- launch ----------------------------------------------------
extern "C" void kernel_launch(void* const* d_in, const int* in_sizes, int n_in,
                              void* d_out, int out_size) {
    const float* x     = (const float*)d_in[0];
    const int*   ei    = (const int*)d_in[1];      // int64 in reference -> int32 in harness
    const float* W     = (const float*)d_in[2];
    const float* att_s = (const float*)d_in[3];
    const float* att_d = (const float*)d_in[4];
    const float* bias  = (const float*)d_in[5];
    const float* gamma = (const float*)d_in[6];
    const float* beta  = (const float*)d_in[7];
    float* out = (float*)d_out;

    const int N = in_sizes[0] / DIM;       // 100000
    const int E = in_sizes[1] / 2;         // 1600000

    k_gemm <<<(N + GBM - 1) / GBM, 256>>>(x, W, N);
    k_asd  <<<(N * 32 + 255) / 256, 256>>>(att_s, att_d, N);
    k_init <<<(N * DIM + 255) / 256, 256>>>(N);
    k_max  <<<(E * HEADS + 255) / 256, 256>>>(ei, E);
    k_acc  <<<(E * 32 + 255) / 256, 256>>>(ei, E);
    k_final<<<N, DIM>>>(bias, gamma, beta, out, N);
}

// round 8
// speedup vs baseline: 1.5443x; 1.5443x over previous
#include <cuda_runtime.h>
#include <cuda_bf16.h>
#include <cstdint>

#define N_NODES 100000
#define HEADS 8
#define OUT_CH 16
#define DIM 128            // IN_CH == OUT_DIM == 128
#define NEG_SLOPE 0.2f
#define LN_EPS 1e-5f

// ---------------- scratch (device globals; no allocation allowed) ----------
__device__ float g_h   [(size_t)N_NODES * DIM];   // x @ W            51.2 MB
__device__ float g_agg [(size_t)N_NODES * DIM];   // unnorm. message  51.2 MB
__device__ float g_as  [N_NODES * HEADS];         // <h, att_src>
__device__ float g_ad  [N_NODES * HEADS];         // <h, att_dst>
__device__ float g_den [N_NODES * HEADS];         // softmax denom (unnorm)

__device__ __forceinline__ float leaky(float v) { return v > 0.f ? v : NEG_SLOPE * v; }

// ---------------- K1: h = x @ W  (128x128 block tile, 8x8 per thread) -------
#define GBM 128
#define GBK 16
__global__ __launch_bounds__(256) void k_gemm(const float* __restrict__ x,
                                              const float* __restrict__ W, int N) {
    __shared__ __align__(16) float As[GBK][GBM + 4];
    __shared__ __align__(16) float Bs[GBK][DIM];
    const int tid = threadIdx.x;
    const int row0 = blockIdx.x * GBM;
    const int tx = tid & 15, ty = tid >> 4;
    const int tm0 = ty * 8, tn0 = tx * 8;
    float acc[8][8] = {};

    for (int k0 = 0; k0 < DIM; k0 += GBK) {
#pragma unroll
        for (int i = 0; i < 2; i++) {
            int idx = tid * 2 + i;          // 0..511
            int r = idx >> 2, c4 = idx & 3;
            int gr = row0 + r;
            float4 v = make_float4(0.f, 0.f, 0.f, 0.f);
            if (gr < N) v = *(const float4*)&x[(size_t)gr * DIM + k0 + c4 * 4];
            As[c4 * 4 + 0][r] = v.x;
            As[c4 * 4 + 1][r] = v.y;
            As[c4 * 4 + 2][r] = v.z;
            As[c4 * 4 + 3][r] = v.w;
        }
#pragma unroll
        for (int i = 0; i < 2; i++) {
            int idx = tid * 2 + i;
            int r = idx >> 5, c4 = idx & 31;
            *(float4*)&Bs[r][c4 * 4] = *(const float4*)&W[(size_t)(k0 + r) * DIM + c4 * 4];
        }
        __syncthreads();
#pragma unroll
        for (int k = 0; k < GBK; k++) {
            float a[8], b[8];
            *(float4*)&a[0] = *(float4*)&As[k][tm0];
            *(float4*)&a[4] = *(float4*)&As[k][tm0 + 4];
            *(float4*)&b[0] = *(float4*)&Bs[k][tn0];
            *(float4*)&b[4] = *(float4*)&Bs[k][tn0 + 4];
#pragma unroll
            for (int i = 0; i < 8; i++)
#pragma unroll
                for (int j = 0; j < 8; j++) acc[i][j] += a[i] * b[j];
        }
        __syncthreads();
    }
#pragma unroll
    for (int i = 0; i < 8; i++) {
        int gr = row0 + tm0 + i;
        if (gr < N) {
            *(float4*)&g_h[(size_t)gr * DIM + tn0]     = *(float4*)&acc[i][0];
            *(float4*)&g_h[(size_t)gr * DIM + tn0 + 4] = *(float4*)&acc[i][4];
        }
    }
}

// ---------------- K2: per-node attention coefficients (warp per node) -------
__global__ __launch_bounds__(256) void k_asd(const float* __restrict__ att_s,
                                             const float* __restrict__ att_d, int N) {
    int w = (blockIdx.x * blockDim.x + threadIdx.x) >> 5;
    int lane = threadIdx.x & 31;
    if (w >= N) return;
    float4 hv = *(const float4*)&g_h[(size_t)w * DIM + lane * 4];
    float4 a = *(const float4*)&att_s[lane * 4];
    float4 b = *(const float4*)&att_d[lane * 4];
    float ps = hv.x * a.x + hv.y * a.y + hv.z * a.z + hv.w * a.w;
    float pd = hv.x * b.x + hv.y * b.y + hv.z * b.z + hv.w * b.w;
    ps += __shfl_xor_sync(0xffffffffu, ps, 1);
    ps += __shfl_xor_sync(0xffffffffu, ps, 2);
    pd += __shfl_xor_sync(0xffffffffu, pd, 1);
    pd += __shfl_xor_sync(0xffffffffu, pd, 2);
    if ((lane & 3) == 0) {
        g_as[w * HEADS + (lane >> 2)] = ps;
        g_ad[w * HEADS + (lane >> 2)] = pd;
    }
}

// ---------------- K3: init agg=0, den=0 -------------------------------------
__global__ __launch_bounds__(256) void k_init(int N) {
    int tid = blockIdx.x * blockDim.x + threadIdx.x;
    if (tid < N * DIM) g_agg[tid] = 0.f;
    if (tid < N * HEADS) g_den[tid] = 0.f;
}

// ---------------- K4: edge accumulate (warp per edge, no max needed) --------
__global__ __launch_bounds__(256) void k_acc(const int* __restrict__ ei, int E) {
    int w = (blockIdx.x * blockDim.x + threadIdx.x) >> 5;
    int lane = threadIdx.x & 31;
    if (w >= E) return;
    int src = 0, dst = 0;
    if (lane == 0) {
        src = ei[w];
        dst = ei[E + w];
    }
    src = __shfl_sync(0xffffffffu, src, 0);
    dst = __shfl_sync(0xffffffffu, dst, 0);

    float ex = 0.f;
    if (lane < HEADS) {
        ex = __expf(leaky(g_as[src * HEADS + lane] + g_ad[dst * HEADS + lane]));
        atomicAdd(&g_den[dst * HEADS + lane], ex);
    }
    // lane handles channels [4*lane, 4*lane+4) -> head = lane/4
    float exh = __shfl_sync(0xffffffffu, ex, lane >> 2);
    float4 hv = *(const float4*)&g_h[(size_t)src * DIM + lane * 4];
    size_t gp = __cvta_generic_to_global(&g_agg[(size_t)dst * DIM + lane * 4]);
    asm volatile("red.global.add.v4.f32 [%0], {%1,%2,%3,%4};"
                 :: "l"(gp), "f"(exh * hv.x), "f"(exh * hv.y),
                    "f"(exh * hv.z), "f"(exh * hv.w)
                 : "memory");
}

// ---------------- K5: self-loop + normalize + bias + LN + ELU ---------------
__global__ __launch_bounds__(128) void k_final(const float* __restrict__ bias,
                                               const float* __restrict__ gamma,
                                               const float* __restrict__ beta,
                                               float* __restrict__ out, int N) {
    int i = blockIdx.x;
    int ch = threadIdx.x;          // 0..127
    int hd = ch >> 4;
    float exs = __expf(leaky(g_as[i * HEADS + hd] + g_ad[i * HEADS + hd]));  // self-loop
    float den = g_den[i * HEADS + hd] + exs;
    float val = (g_agg[(size_t)i * DIM + ch] + exs * g_h[(size_t)i * DIM + ch]) / den;
    val += bias[ch];

    // block LayerNorm over 128 channels
    __shared__ float ssum[4], ssq[4];
    float s = val, q = val * val;
#pragma unroll
    for (int o = 16; o > 0; o >>= 1) {
        s += __shfl_xor_sync(0xffffffffu, s, o);
        q += __shfl_xor_sync(0xffffffffu, q, o);
    }
    if ((ch & 31) == 0) { ssum[ch >> 5] = s; ssq[ch >> 5] = q; }
    __syncthreads();
    float S = ssum[0] + ssum[1] + ssum[2] + ssum[3];
    float Q = ssq[0] + ssq[1] + ssq[2] + ssq[3];
    float mu = S * (1.f / DIM);
    float var = Q * (1.f / DIM) - mu * mu;
    float y = (val - mu) * rsqrtf(var + LN_EPS) * gamma[ch] + beta[ch];
    out[(size_t)i * DIM + ch] = y > 0.f ? y : (__expf(y) - 1.f);
}

// ---------------- launch ----------------------------------------------------
extern "C" void kernel_launch(void* const* d_in, const int* in_sizes, int n_in,
                              void* d_out, int out_size) {
    const float* x     = (const float*)d_in[0];
    const int*   ei    = (const int*)d_in[1];      // int64 in reference -> int32 in harness
    const float* W     = (const float*)d_in[2];
    const float* att_s = (const float*)d_in[3];
    const float* att_d = (const float*)d_in[4];
    const float* bias  = (const float*)d_in[5];
    const float* gamma = (const float*)d_in[6];
    const float* beta  = (const float*)d_in[7];
    float* out = (float*)d_out;

    const int N = in_sizes[0] / DIM;       // 100000
    const int E = in_sizes[1] / 2;         // 1600000

    k_init <<<(N * DIM + 255) / 256, 256>>>(N);
    k_gemm <<<(N + GBM - 1) / GBM, 256>>>(x, W, N);
    k_asd  <<<(N * 32 + 255) / 256, 256>>>(att_s, att_d, N);
    k_acc  <<<(E * 32 + 255) / 256, 256>>>(ei, E);
    k_final<<<N, DIM>>>(bias, gamma, beta, out, N);
}

// round 9
// speedup vs baseline: 2.1029x; 1.3618x over previous
#include <cuda_runtime.h>
#include <cuda_bf16.h>
#include <cstdint>

#define N_NODES 100000
#define HEADS 8
#define OUT_CH 16
#define DIM 128            // IN_CH == OUT_DIM == 128
#define NEG_SLOPE 0.2f
#define LN_EPS 1e-5f

// ---------------- scratch (device globals; no allocation allowed) ----------
__device__ float g_h   [(size_t)N_NODES * DIM];   // x @ W            51.2 MB
__device__ float g_agg [(size_t)N_NODES * DIM];   // unnorm. message  51.2 MB
__device__ float g_as  [N_NODES * HEADS];         // <h, att_src>
__device__ float g_ad  [N_NODES * HEADS];         // <h, att_dst>
__device__ float g_den [N_NODES * HEADS];         // softmax denom (unnorm)

__device__ __forceinline__ float leaky(float v) { return v > 0.f ? v : NEG_SLOPE * v; }

// ---------------- K1: h = x @ W  (128x128 block tile, 8x8 per thread) -------
//                 epilogue also zeroes g_agg for the same tile
#define GBM 128
#define GBK 16
__global__ __launch_bounds__(256) void k_gemm(const float* __restrict__ x,
                                              const float* __restrict__ W, int N) {
    __shared__ __align__(16) float As[GBK][GBM + 4];
    __shared__ __align__(16) float Bs[GBK][DIM];
    const int tid = threadIdx.x;
    const int row0 = blockIdx.x * GBM;
    const int tx = tid & 15, ty = tid >> 4;
    const int tm0 = ty * 8, tn0 = tx * 8;
    float acc[8][8] = {};

    for (int k0 = 0; k0 < DIM; k0 += GBK) {
#pragma unroll
        for (int i = 0; i < 2; i++) {
            int idx = tid * 2 + i;          // 0..511
            int r = idx >> 2, c4 = idx & 3;
            int gr = row0 + r;
            float4 v = make_float4(0.f, 0.f, 0.f, 0.f);
            if (gr < N) v = *(const float4*)&x[(size_t)gr * DIM + k0 + c4 * 4];
            As[c4 * 4 + 0][r] = v.x;
            As[c4 * 4 + 1][r] = v.y;
            As[c4 * 4 + 2][r] = v.z;
            As[c4 * 4 + 3][r] = v.w;
        }
#pragma unroll
        for (int i = 0; i < 2; i++) {
            int idx = tid * 2 + i;
            int r = idx >> 5, c4 = idx & 31;
            *(float4*)&Bs[r][c4 * 4] = *(const float4*)&W[(size_t)(k0 + r) * DIM + c4 * 4];
        }
        __syncthreads();
#pragma unroll
        for (int k = 0; k < GBK; k++) {
            float a[8], b[8];
            *(float4*)&a[0] = *(float4*)&As[k][tm0];
            *(float4*)&a[4] = *(float4*)&As[k][tm0 + 4];
            *(float4*)&b[0] = *(float4*)&Bs[k][tn0];
            *(float4*)&b[4] = *(float4*)&Bs[k][tn0 + 4];
#pragma unroll
            for (int i = 0; i < 8; i++)
#pragma unroll
                for (int j = 0; j < 8; j++) acc[i][j] += a[i] * b[j];
        }
        __syncthreads();
    }
    const float4 z4 = make_float4(0.f, 0.f, 0.f, 0.f);
#pragma unroll
    for (int i = 0; i < 8; i++) {
        int gr = row0 + tm0 + i;
        if (gr < N) {
            *(float4*)&g_h[(size_t)gr * DIM + tn0]       = *(float4*)&acc[i][0];
            *(float4*)&g_h[(size_t)gr * DIM + tn0 + 4]   = *(float4*)&acc[i][4];
            *(float4*)&g_agg[(size_t)gr * DIM + tn0]     = z4;
            *(float4*)&g_agg[(size_t)gr * DIM + tn0 + 4] = z4;
        }
    }
}

// ---------------- K2: per-node attention coefficients (warp per node) -------
//                 also zeroes g_den
__global__ __launch_bounds__(256) void k_asd(const float* __restrict__ att_s,
                                             const float* __restrict__ att_d, int N) {
    int w = (blockIdx.x * blockDim.x + threadIdx.x) >> 5;
    int lane = threadIdx.x & 31;
    if (w >= N) return;
    float4 hv = *(const float4*)&g_h[(size_t)w * DIM + lane * 4];
    float4 a = *(const float4*)&att_s[lane * 4];
    float4 b = *(const float4*)&att_d[lane * 4];
    float ps = hv.x * a.x + hv.y * a.y + hv.z * a.z + hv.w * a.w;
    float pd = hv.x * b.x + hv.y * b.y + hv.z * b.z + hv.w * b.w;
    ps += __shfl_xor_sync(0xffffffffu, ps, 1);
    ps += __shfl_xor_sync(0xffffffffu, ps, 2);
    pd += __shfl_xor_sync(0xffffffffu, pd, 1);
    pd += __shfl_xor_sync(0xffffffffu, pd, 2);
    if ((lane & 3) == 0) {
        int hd = lane >> 2;
        g_as [w * HEADS + hd] = ps;
        g_ad [w * HEADS + hd] = pd;
        g_den[w * HEADS + hd] = 0.f;
    }
}

// ---------------- K3: edge accumulate (4 edges per warp) --------------------
#define EPW 4
__global__ __launch_bounds__(256) void k_acc(const int* __restrict__ ei, int E) {
    int warp = (blockIdx.x * blockDim.x + threadIdx.x) >> 5;
    int lane = threadIdx.x & 31;
    int e0 = warp * EPW;
    if (e0 >= E) return;

    // lanes 0..3 load src of edges e0..e0+3; lanes 4..7 load dst
    int idx = 0;
    if (lane < 4) {
        int e = e0 + lane;
        idx = (e < E) ? ei[e] : 0;
    } else if (lane < 8) {
        int e = e0 + lane - 4;
        idx = (e < E) ? ei[E + e] : 0;
    }

    // logit phase: lane = edge_local*8 + head  (full 32-lane utilization)
    int el = lane >> 3;       // 0..3
    int hd = lane & 7;        // 0..7
    int src_l = __shfl_sync(0xffffffffu, idx, el);
    int dst_l = __shfl_sync(0xffffffffu, idx, 4 + el);
    float ex = 0.f;
    if (e0 + el < E) {
        ex = __expf(leaky(g_as[src_l * HEADS + hd] + g_ad[dst_l * HEADS + hd]));
        atomicAdd(&g_den[dst_l * HEADS + hd], ex);
    }

    // gather/scatter phase: 4 independent 512B gathers + v4 REDs (MLP=4)
#pragma unroll
    for (int e = 0; e < EPW; e++) {
        if (e0 + e >= E) break;
        int src = __shfl_sync(0xffffffffu, idx, e);
        int dst = __shfl_sync(0xffffffffu, idx, 4 + e);
        float exh = __shfl_sync(0xffffffffu, ex, e * 8 + (lane >> 2));
        float4 hv = *(const float4*)&g_h[(size_t)src * DIM + lane * 4];
        size_t gp = __cvta_generic_to_global(&g_agg[(size_t)dst * DIM + lane * 4]);
        asm volatile("red.global.add.v4.f32 [%0], {%1,%2,%3,%4};"
                     :: "l"(gp), "f"(exh * hv.x), "f"(exh * hv.y),
                        "f"(exh * hv.z), "f"(exh * hv.w)
                     : "memory");
    }
}

// ---------------- K4: self-loop + normalize + bias + LN + ELU ---------------
__global__ __launch_bounds__(128) void k_final(const float* __restrict__ bias,
                                               const float* __restrict__ gamma,
                                               const float* __restrict__ beta,
                                               float* __restrict__ out, int N) {
    int i = blockIdx.x;
    int ch = threadIdx.x;          // 0..127
    int hd = ch >> 4;
    float exs = __expf(leaky(g_as[i * HEADS + hd] + g_ad[i * HEADS + hd]));  // self-loop
    float den = g_den[i * HEADS + hd] + exs;
    float val = (g_agg[(size_t)i * DIM + ch] + exs * g_h[(size_t)i * DIM + ch]) / den;
    val += bias[ch];

    // block LayerNorm over 128 channels
    __shared__ float ssum[4], ssq[4];
    float s = val, q = val * val;
#pragma unroll
    for (int o = 16; o > 0; o >>= 1) {
        s += __shfl_xor_sync(0xffffffffu, s, o);
        q += __shfl_xor_sync(0xffffffffu, q, o);
    }
    if ((ch & 31) == 0) { ssum[ch >> 5] = s; ssq[ch >> 5] = q; }
    __syncthreads();
    float S = ssum[0] + ssum[1] + ssum[2] + ssum[3];
    float Q = ssq[0] + ssq[1] + ssq[2] + ssq[3];
    float mu = S * (1.f / DIM);
    float var = Q * (1.f / DIM) - mu * mu;
    float y = (val - mu) * rsqrtf(var + LN_EPS) * gamma[ch] + beta[ch];
    out[(size_t)i * DIM + ch] = y > 0.f ? y : (__expf(y) - 1.f);
}

// ---------------- launch ----------------------------------------------------
extern "C" void kernel_launch(void* const* d_in, const int* in_sizes, int n_in,
                              void* d_out, int out_size) {
    const float* x     = (const float*)d_in[0];
    const int*   ei    = (const int*)d_in[1];      // int64 in reference -> int32 in harness
    const float* W     = (const float*)d_in[2];
    const float* att_s = (const float*)d_in[3];
    const float* att_d = (const float*)d_in[4];
    const float* bias  = (const float*)d_in[5];
    const float* gamma = (const float*)d_in[6];
    const float* beta  = (const float*)d_in[7];
    float* out = (float*)d_out;

    const int N = in_sizes[0] / DIM;       // 100000
    const int E = in_sizes[1] / 2;         // 1600000

    k_gemm <<<(N + GBM - 1) / GBM, 256>>>(x, W, N);
    k_asd  <<<(N * 32 + 255) / 256, 256>>>(att_s, att_d, N);
    int warps = (E + EPW - 1) / EPW;
    k_acc  <<<(warps * 32 + 255) / 256, 256>>>(ei, E);
    k_final<<<N, DIM>>>(bias, gamma, beta, out, N);
}

// round 10
// speedup vs baseline: 2.3320x; 1.1089x over previous
#include <cuda_runtime.h>
#include <cuda_bf16.h>
#include <cstdint>

#define N_NODES 100000
#define HEADS 8
#define OUT_CH 16
#define DIM 128            // IN_CH == OUT_DIM == 128
#define NEG_SLOPE 0.2f
#define LN_EPS 1e-5f

// ---------------- scratch (device globals; no allocation allowed) ----------
__device__ float g_h   [(size_t)N_NODES * DIM];   // x @ W            51.2 MB
__device__ float g_agg [(size_t)N_NODES * DIM];   // unnorm. message  51.2 MB
__device__ float g_as  [N_NODES * HEADS];         // <h, att_src>
__device__ float g_ad  [N_NODES * HEADS];         // <h, att_dst>
__device__ float g_den [N_NODES * HEADS];         // softmax denom (unnorm)

__device__ __forceinline__ float leaky(float v) { return v > 0.f ? v : NEG_SLOPE * v; }

// ---------------- K1: h = x @ W  (128x128 block tile, 8x8 per thread) -------
//                 epilogue also zeroes g_agg for the same tile
#define GBM 128
#define GBK 16
__global__ __launch_bounds__(256) void k_gemm(const float* __restrict__ x,
                                              const float* __restrict__ W, int N) {
    __shared__ __align__(16) float As[GBK][GBM + 4];
    __shared__ __align__(16) float Bs[GBK][DIM];
    const int tid = threadIdx.x;
    const int row0 = blockIdx.x * GBM;
    const int tx = tid & 15, ty = tid >> 4;
    const int tm0 = ty * 8, tn0 = tx * 8;
    float acc[8][8] = {};

    for (int k0 = 0; k0 < DIM; k0 += GBK) {
#pragma unroll
        for (int i = 0; i < 2; i++) {
            int idx = tid * 2 + i;          // 0..511
            int r = idx >> 2, c4 = idx & 3;
            int gr = row0 + r;
            float4 v = make_float4(0.f, 0.f, 0.f, 0.f);
            if (gr < N) v = *(const float4*)&x[(size_t)gr * DIM + k0 + c4 * 4];
            As[c4 * 4 + 0][r] = v.x;
            As[c4 * 4 + 1][r] = v.y;
            As[c4 * 4 + 2][r] = v.z;
            As[c4 * 4 + 3][r] = v.w;
        }
#pragma unroll
        for (int i = 0; i < 2; i++) {
            int idx = tid * 2 + i;
            int r = idx >> 5, c4 = idx & 31;
            *(float4*)&Bs[r][c4 * 4] = *(const float4*)&W[(size_t)(k0 + r) * DIM + c4 * 4];
        }
        __syncthreads();
#pragma unroll
        for (int k = 0; k < GBK; k++) {
            float a[8], b[8];
            *(float4*)&a[0] = *(float4*)&As[k][tm0];
            *(float4*)&a[4] = *(float4*)&As[k][tm0 + 4];
            *(float4*)&b[0] = *(float4*)&Bs[k][tn0];
            *(float4*)&b[4] = *(float4*)&Bs[k][tn0 + 4];
#pragma unroll
            for (int i = 0; i < 8; i++)
#pragma unroll
                for (int j = 0; j < 8; j++) acc[i][j] += a[i] * b[j];
        }
        __syncthreads();
    }
    const float4 z4 = make_float4(0.f, 0.f, 0.f, 0.f);
#pragma unroll
    for (int i = 0; i < 8; i++) {
        int gr = row0 + tm0 + i;
        if (gr < N) {
            *(float4*)&g_h[(size_t)gr * DIM + tn0]       = *(float4*)&acc[i][0];
            *(float4*)&g_h[(size_t)gr * DIM + tn0 + 4]   = *(float4*)&acc[i][4];
            *(float4*)&g_agg[(size_t)gr * DIM + tn0]     = z4;
            *(float4*)&g_agg[(size_t)gr * DIM + tn0 + 4] = z4;
        }
    }
}

// ---------------- K2: per-node attention coefficients (warp per node) -------
//                 also zeroes g_den
__global__ __launch_bounds__(256) void k_asd(const float* __restrict__ att_s,
                                             const float* __restrict__ att_d, int N) {
    int w = (blockIdx.x * blockDim.x + threadIdx.x) >> 5;
    int lane = threadIdx.x & 31;
    if (w >= N) return;
    float4 hv = *(const float4*)&g_h[(size_t)w * DIM + lane * 4];
    float4 a = *(const float4*)&att_s[lane * 4];
    float4 b = *(const float4*)&att_d[lane * 4];
    float ps = hv.x * a.x + hv.y * a.y + hv.z * a.z + hv.w * a.w;
    float pd = hv.x * b.x + hv.y * b.y + hv.z * b.z + hv.w * b.w;
    ps += __shfl_xor_sync(0xffffffffu, ps, 1);
    ps += __shfl_xor_sync(0xffffffffu, ps, 2);
    pd += __shfl_xor_sync(0xffffffffu, pd, 1);
    pd += __shfl_xor_sync(0xffffffffu, pd, 2);
    if ((lane & 3) == 0) {
        int hd = lane >> 2;
        g_as [w * HEADS + hd] = ps;
        g_ad [w * HEADS + hd] = pd;
        g_den[w * HEADS + hd] = 0.f;
    }
}

// ---------------- K3: edge accumulate (8 edges per warp, MLP=8) -------------
#define EPW 8
__global__ __launch_bounds__(256) void k_acc(const int* __restrict__ ei, int E) {
    int warp = (blockIdx.x * blockDim.x + threadIdx.x) >> 5;
    int lane = threadIdx.x & 31;
    int e0 = warp * EPW;
    if (e0 >= E) return;

    // lanes 0..7 load src of edges e0..e0+7; lanes 8..15 load dst
    int idx = 0;
    if (lane < 8) {
        int e = e0 + lane;
        idx = (e < E) ? ei[e] : 0;
    } else if (lane < 16) {
        int e = e0 + lane - 8;
        idx = (e < E) ? ei[E + e] : 0;
    }

    // logit phase: 64 (edge,head) pairs over 2 iterations of 32 lanes
    // iteration j covers edges j*4 .. j*4+3; lane = (edge&3)*8 + head
    int hd = lane & 7;
    float ex[2];
#pragma unroll
    for (int j = 0; j < 2; j++) {
        int el = j * 4 + (lane >> 3);     // 0..7
        int src_l = __shfl_sync(0xffffffffu, idx, el);
        int dst_l = __shfl_sync(0xffffffffu, idx, 8 + el);
        ex[j] = 0.f;
        if (e0 + el < E) {
            ex[j] = __expf(leaky(g_as[src_l * HEADS + hd] + g_ad[dst_l * HEADS + hd]));
            atomicAdd(&g_den[dst_l * HEADS + hd], ex[j]);
        }
    }

    // gather/scatter phase: 8 independent 512B gathers + v4 REDs (MLP=8)
#pragma unroll
    for (int e = 0; e < EPW; e++) {
        if (e0 + e >= E) break;
        int src = __shfl_sync(0xffffffffu, idx, e);
        int dst = __shfl_sync(0xffffffffu, idx, 8 + e);
        // ex for (edge e, head lane>>2) lives in ex[e>>2] of lane (e&3)*8 + head
        float exh = __shfl_sync(0xffffffffu, ex[e >> 2], (e & 3) * 8 + (lane >> 2));
        float4 hv = *(const float4*)&g_h[(size_t)src * DIM + lane * 4];
        size_t gp = __cvta_generic_to_global(&g_agg[(size_t)dst * DIM + lane * 4]);
        asm volatile("red.global.add.v4.f32 [%0], {%1,%2,%3,%4};"
                     :: "l"(gp), "f"(exh * hv.x), "f"(exh * hv.y),
                        "f"(exh * hv.z), "f"(exh * hv.w)
                     : "memory");
    }
}

// ---------------- K4: warp per node, float4 per lane ------------------------
__global__ __launch_bounds__(256) void k_final(const float* __restrict__ bias,
                                               const float* __restrict__ gamma,
                                               const float* __restrict__ beta,
                                               float* __restrict__ out, int N) {
    int i = (blockIdx.x * blockDim.x + threadIdx.x) >> 5;    // node
    int lane = threadIdx.x & 31;
    if (i >= N) return;
    int hd = lane >> 2;                                      // head for these 4 ch

    float exs = __expf(leaky(g_as[i * HEADS + hd] + g_ad[i * HEADS + hd]));
    float rden = __frcp_rn(g_den[i * HEADS + hd] + exs);

    float4 ag = *(const float4*)&g_agg[(size_t)i * DIM + lane * 4];
    float4 hv = *(const float4*)&g_h[(size_t)i * DIM + lane * 4];
    float4 bi = *(const float4*)&bias[lane * 4];
    float4 v;
    v.x = (ag.x + exs * hv.x) * rden + bi.x;
    v.y = (ag.y + exs * hv.y) * rden + bi.y;
    v.z = (ag.z + exs * hv.z) * rden + bi.z;
    v.w = (ag.w + exs * hv.w) * rden + bi.w;

    float s = v.x + v.y + v.z + v.w;
    float q = v.x * v.x + v.y * v.y + v.z * v.z + v.w * v.w;
#pragma unroll
    for (int o = 16; o > 0; o >>= 1) {
        s += __shfl_xor_sync(0xffffffffu, s, o);
        q += __shfl_xor_sync(0xffffffffu, q, o);
    }
    float mu = s * (1.f / DIM);
    float rsd = rsqrtf(q * (1.f / DIM) - mu * mu + LN_EPS);

    float4 ga = *(const float4*)&gamma[lane * 4];
    float4 be = *(const float4*)&beta[lane * 4];
    float4 y;
    y.x = (v.x - mu) * rsd * ga.x + be.x;
    y.y = (v.y - mu) * rsd * ga.y + be.y;
    y.z = (v.z - mu) * rsd * ga.z + be.z;
    y.w = (v.w - mu) * rsd * ga.w + be.w;
    y.x = y.x > 0.f ? y.x : (__expf(y.x) - 1.f);
    y.y = y.y > 0.f ? y.y : (__expf(y.y) - 1.f);
    y.z = y.z > 0.f ? y.z : (__expf(y.z) - 1.f);
    y.w = y.w > 0.f ? y.w : (__expf(y.w) - 1.f);
    *(float4*)&out[(size_t)i * DIM + lane * 4] = y;
}

// ---------------- launch ----------------------------------------------------
extern "C" void kernel_launch(void* const* d_in, const int* in_sizes, int n_in,
                              void* d_out, int out_size) {
    const float* x     = (const float*)d_in[0];
    const int*   ei    = (const int*)d_in[1];      // int64 in reference -> int32 in harness
    const float* W     = (const float*)d_in[2];
    const float* att_s = (const float*)d_in[3];
    const float* att_d = (const float*)d_in[4];
    const float* bias  = (const float*)d_in[5];
    const float* gamma = (const float*)d_in[6];
    const float* beta  = (const float*)d_in[7];
    float* out = (float*)d_out;

    const int N = in_sizes[0] / DIM;       // 100000
    const int E = in_sizes[1] / 2;         // 1600000

    k_gemm <<<(N + GBM - 1) / GBM, 256>>>(x, W, N);
    k_asd  <<<(N * 32 + 255) / 256, 256>>>(att_s, att_d, N);
    int warps = (E + EPW - 1) / EPW;
    k_acc  <<<(warps * 32 + 255) / 256, 256>>>(ei, E);
    k_final<<<(N * 32 + 255) / 256, 256>>>(bias, gamma, beta, out, N);
}

// round 13
// speedup vs baseline: 2.4277x; 1.0410x over previous
#include <cuda_runtime.h>
#include <cuda_bf16.h>
#include <cstdint>

#define N_NODES 100000
#define HEADS 8
#define OUT_CH 16
#define DIM 128            // IN_CH == OUT_DIM == 128
#define NEG_SLOPE 0.2f
#define LN_EPS 1e-5f

// ---------------- scratch (device globals; no allocation allowed) ----------
__device__ float g_h   [(size_t)N_NODES * DIM];   // x @ W            51.2 MB
__device__ float g_agg [(size_t)N_NODES * DIM];   // unnorm. message  51.2 MB
__device__ float g_as  [N_NODES * HEADS];         // <h, att_src>
__device__ float g_ad  [N_NODES * HEADS];         // <h, att_dst>
__device__ float g_den [N_NODES * HEADS];         // softmax denom (unnorm)

__device__ __forceinline__ float leaky(float v) { return v > 0.f ? v : NEG_SLOPE * v; }
__device__ __forceinline__ uint32_t pack_bf2(__nv_bfloat16 lo, __nv_bfloat16 hi) {
    return (uint32_t)__bfloat16_as_ushort(lo) | ((uint32_t)__bfloat16_as_ushort(hi) << 16);
}

// mma.sync m16n8k16 row.col f32.bf16.bf16.f32 (baseline PTX, works on compute_103)
#define MMA16816(C, a0, a1, a2, a3, b0, b1) \
    asm volatile("mma.sync.aligned.m16n8k16.row.col.f32.bf16.bf16.f32 " \
                 "{%0,%1,%2,%3}, {%4,%5,%6,%7}, {%8,%9}, {%0,%1,%2,%3};" \
                 : "+f"((C)[0]), "+f"((C)[1]), "+f"((C)[2]), "+f"((C)[3]) \
                 : "r"(a0), "r"(a1), "r"(a2), "r"(a3), "r"(b0), "r"(b1))

// ---------------- K1: split-bf16 HMMA GEMM + fused a_s/a_d + zero agg/den ---
// Block: 128 rows x 128 cols, K=128. 8 warps, each warp: 16 rows, all 128 cols.
// W packed in smem as fragment-ready bf16x2 uint2 entries:
//   entry(n, ks, q) at uint2 index n*33 + ks*4 + q  (pad 33 kills bank conflicts)
//   .x = bf16x2 of W[ks*16+q*2, ks*16+q*2+1][n]   (b0 of the fragment)
//   .y = bf16x2 of W[ks*16+8+q*2, +1][n]          (b1 of the fragment)
#define WSM_U32 (128 * 33 * 2)      // uint32 words per precision image
#define SMEM_BYTES (2 * WSM_U32 * 4)

__global__ __launch_bounds__(256) void k_gemm(const float* __restrict__ x,
                                              const float* __restrict__ W,
                                              const float* __restrict__ att_s,
                                              const float* __restrict__ att_d, int N) {
    extern __shared__ uint32_t smw[];
    uint32_t* whi = smw;
    uint32_t* wlo = smw + WSM_U32;

    const int tid = threadIdx.x;
    const int lane = tid & 31, w = tid >> 5;
    const int g = lane >> 2, q = lane & 3;

    // pack W -> smem (hi/lo split), coalesced global reads
    for (int idx = tid; idx < 128 * 64; idx += 256) {
        int k2 = idx >> 7, n = idx & 127;            // k2: bf16x2 pair index along K
        float w0 = W[(2 * k2) * 128 + n];
        float w1 = W[(2 * k2 + 1) * 128 + n];
        __nv_bfloat16 h0 = __float2bfloat16(w0), h1 = __float2bfloat16(w1);
        __nv_bfloat16 l0 = __float2bfloat16(w0 - __bfloat162float(h0));
        __nv_bfloat16 l1 = __float2bfloat16(w1 - __bfloat162float(h1));
        int ks = k2 >> 3, r = k2 & 7;                // r<4 -> .x (b0), r>=4 -> .y (b1)
        int ent = ((n * 33 + ks * 4 + (r & 3)) << 1) + (r >> 2);
        whi[ent] = pack_bf2(h0, h1);
        wlo[ent] = pack_bf2(l0, l1);
    }
    __syncthreads();

    const int r0g = blockIdx.x * 128 + w * 16 + g;   // rows g and g+8 of warp tile
    const int r1g = r0g + 8;
    const bool v0 = r0g < N, v1 = r1g < N;
    const float* xr0 = &x[(size_t)r0g * DIM];
    const float* xr1 = &x[(size_t)r1g * DIM];

    float c[16][4];
#pragma unroll
    for (int j = 0; j < 16; j++) { c[j][0] = c[j][1] = c[j][2] = c[j][3] = 0.f; }

    const float2 z2 = make_float2(0.f, 0.f);
#pragma unroll
    for (int ks = 0; ks < 8; ks++) {
        int c0 = ks * 16 + q * 2;
        float2 fa = v0 ? *(const float2*)&xr0[c0]     : z2;   // a0: row g,   k c0,c0+1
        float2 fc = v1 ? *(const float2*)&xr1[c0]     : z2;   // a1: row g+8
        float2 fb = v0 ? *(const float2*)&xr0[c0 + 8] : z2;   // a2: row g,   k +8,+9
        float2 fd = v1 ? *(const float2*)&xr1[c0 + 8] : z2;   // a3: row g+8
        __nv_bfloat16 ha0 = __float2bfloat16(fa.x), ha1 = __float2bfloat16(fa.y);
        __nv_bfloat16 hc0 = __float2bfloat16(fc.x), hc1 = __float2bfloat16(fc.y);
        __nv_bfloat16 hb0 = __float2bfloat16(fb.x), hb1 = __float2bfloat16(fb.y);
        __nv_bfloat16 hd0 = __float2bfloat16(fd.x), hd1 = __float2bfloat16(fd.y);
        uint32_t ah0 = pack_bf2(ha0, ha1), ah1 = pack_bf2(hc0, hc1);
        uint32_t ah2 = pack_bf2(hb0, hb1), ah3 = pack_bf2(hd0, hd1);
        uint32_t al0 = pack_bf2(__float2bfloat16(fa.x - __bfloat162float(ha0)),
                                __float2bfloat16(fa.y - __bfloat162float(ha1)));
        uint32_t al1 = pack_bf2(__float2bfloat16(fc.x - __bfloat162float(hc0)),
                                __float2bfloat16(fc.y - __bfloat162float(hc1)));
        uint32_t al2 = pack_bf2(__float2bfloat16(fb.x - __bfloat162float(hb0)),
                                __float2bfloat16(fb.y - __bfloat162float(hb1)));
        uint32_t al3 = pack_bf2(__float2bfloat16(fd.x - __bfloat162float(hd0)),
                                __float2bfloat16(fd.y - __bfloat162float(hd1)));
#pragma unroll
        for (int j = 0; j < 16; j++) {
            int ent = (j * 8 + g) * 33 + ks * 4 + q;
            uint2 bh = ((const uint2*)whi)[ent];
            uint2 bl = ((const uint2*)wlo)[ent];
            MMA16816(c[j], ah0, ah1, ah2, ah3, bh.x, bh.y);   // hi*hi
            MMA16816(c[j], ah0, ah1, ah2, ah3, bl.x, bl.y);   // hi*lo
            MMA16816(c[j], al0, al1, al2, al3, bh.x, bh.y);   // lo*hi
        }
    }

    // ---- fused a_s / a_d: thread cols in tile j are j*8+q*2, +1; head = j>>1
    float asr0[8] = {}, asr1[8] = {}, adr0[8] = {}, adr1[8] = {};
#pragma unroll
    for (int j = 0; j < 16; j++) {
        int h = j >> 1;
        int cc = j * 8 + q * 2;
        float s0 = att_s[cc], s1 = att_s[cc + 1];
        float d0 = att_d[cc], d1 = att_d[cc + 1];
        asr0[h] += c[j][0] * s0 + c[j][1] * s1;
        asr1[h] += c[j][2] * s0 + c[j][3] * s1;
        adr0[h] += c[j][0] * d0 + c[j][1] * d1;
        adr1[h] += c[j][2] * d0 + c[j][3] * d1;
    }
#pragma unroll
    for (int h = 0; h < 8; h++) {
        asr0[h] += __shfl_xor_sync(0xffffffffu, asr0[h], 1);
        asr0[h] += __shfl_xor_sync(0xffffffffu, asr0[h], 2);
        asr1[h] += __shfl_xor_sync(0xffffffffu, asr1[h], 1);
        asr1[h] += __shfl_xor_sync(0xffffffffu, asr1[h], 2);
        adr0[h] += __shfl_xor_sync(0xffffffffu, adr0[h], 1);
        adr0[h] += __shfl_xor_sync(0xffffffffu, adr0[h], 2);
        adr1[h] += __shfl_xor_sync(0xffffffffu, adr1[h], 1);
        adr1[h] += __shfl_xor_sync(0xffffffffu, adr1[h], 2);
    }

    // ---- stores: g_h + zero g_agg (float2 per row per tile)
#pragma unroll
    for (int j = 0; j < 16; j++) {
        int cc = j * 8 + q * 2;
        if (v0) {
            *(float2*)&g_h  [(size_t)r0g * DIM + cc] = make_float2(c[j][0], c[j][1]);
            *(float2*)&g_agg[(size_t)r0g * DIM + cc] = z2;
        }
        if (v1) {
            *(float2*)&g_h  [(size_t)r1g * DIM + cc] = make_float2(c[j][2], c[j][3]);
            *(float2*)&g_agg[(size_t)r1g * DIM + cc] = z2;
        }
    }
    if (q == 0) {
        const float4 z4 = make_float4(0.f, 0.f, 0.f, 0.f);
        if (v0) {
            *(float4*)&g_as[r0g * 8]     = make_float4(asr0[0], asr0[1], asr0[2], asr0[3]);
            *(float4*)&g_as[r0g * 8 + 4] = make_float4(asr0[4], asr0[5], asr0[6], asr0[7]);
            *(float4*)&g_ad[r0g * 8]     = make_float4(adr0[0], adr0[1], adr0[2], adr0[3]);
            *(float4*)&g_ad[r0g * 8 + 4] = make_float4(adr0[4], adr0[5], adr0[6], adr0[7]);
            *(float4*)&g_den[r0g * 8]     = z4;
            *(float4*)&g_den[r0g * 8 + 4] = z4;
        }
        if (v1) {
            *(float4*)&g_as[r1g * 8]     = make_float4(asr1[0], asr1[1], asr1[2], asr1[3]);
            *(float4*)&g_as[r1g * 8 + 4] = make_float4(asr1[4], asr1[5], asr1[6], asr1[7]);
            *(float4*)&g_ad[r1g * 8]     = make_float4(adr1[0], adr1[1], adr1[2], adr1[3]);
            *(float4*)&g_ad[r1g * 8 + 4] = make_float4(adr1[4], adr1[5], adr1[6], adr1[7]);
            *(float4*)&g_den[r1g * 8]     = z4;
            *(float4*)&g_den[r1g * 8 + 4] = z4;
        }
    }
}

// ---------------- K2: edge accumulate (8 edges per warp, MLP=8) -------------
#define EPW 8
__global__ __launch_bounds__(256) void k_acc(const int* __restrict__ ei, int E) {
    int warp = (blockIdx.x * blockDim.x + threadIdx.x) >> 5;
    int lane = threadIdx.x & 31;
    int e0 = warp * EPW;
    if (e0 >= E) return;

    int idx = 0;
    if (lane < 8) {
        int e = e0 + lane;
        idx = (e < E) ? ei[e] : 0;
    } else if (lane < 16) {
        int e = e0 + lane - 8;
        idx = (e < E) ? ei[E + e] : 0;
    }

    int hd = lane & 7;
    float ex[2];
#pragma unroll
    for (int j = 0; j < 2; j++) {
        int el = j * 4 + (lane >> 3);
        int src_l = __shfl_sync(0xffffffffu, idx, el);
        int dst_l = __shfl_sync(0xffffffffu, idx, 8 + el);
        ex[j] = 0.f;
        if (e0 + el < E) {
            ex[j] = __expf(leaky(g_as[src_l * HEADS + hd] + g_ad[dst_l * HEADS + hd]));
            atomicAdd(&g_den[dst_l * HEADS + hd], ex[j]);
        }
    }
#pragma unroll
    for (int e = 0; e < EPW; e++) {
        if (e0 + e >= E) break;
        int src = __shfl_sync(0xffffffffu, idx, e);
        int dst = __shfl_sync(0xffffffffu, idx, 8 + e);
        float exh = __shfl_sync(0xffffffffu, ex[e >> 2], (e & 3) * 8 + (lane >> 2));
        float4 hv = *(const float4*)&g_h[(size_t)src * DIM + lane * 4];
        size_t gp = __cvta_generic_to_global(&g_agg[(size_t)dst * DIM + lane * 4]);
        asm volatile("red.global.add.v4.f32 [%0], {%1,%2,%3,%4};"
                     :: "l"(gp), "f"(exh * hv.x), "f"(exh * hv.y),
                        "f"(exh * hv.z), "f"(exh * hv.w)
                     : "memory");
    }
}

// ---------------- K3: warp per node, float4 per lane ------------------------
__global__ __launch_bounds__(256) void k_final(const float* __restrict__ bias,
                                               const float* __restrict__ gamma,
                                               const float* __restrict__ beta,
                                               float* __restrict__ out, int N) {
    int i = (blockIdx.x * blockDim.x + threadIdx.x) >> 5;
    int lane = threadIdx.x & 31;
    if (i >= N) return;
    int hd = lane >> 2;

    float exs = __expf(leaky(g_as[i * HEADS + hd] + g_ad[i * HEADS + hd]));
    float rden = __frcp_rn(g_den[i * HEADS + hd] + exs);

    float4 ag = *(const float4*)&g_agg[(size_t)i * DIM + lane * 4];
    float4 hv = *(const float4*)&g_h[(size_t)i * DIM + lane * 4];
    float4 bi = *(const float4*)&bias[lane * 4];
    float4 v;
    v.x = (ag.x + exs * hv.x) * rden + bi.x;
    v.y = (ag.y + exs * hv.y) * rden + bi.y;
    v.z = (ag.z + exs * hv.z) * rden + bi.z;
    v.w = (ag.w + exs * hv.w) * rden + bi.w;

    float s = v.x + v.y + v.z + v.w;
    float q = v.x * v.x + v.y * v.y + v.z * v.z + v.w * v.w;
#pragma unroll
    for (int o = 16; o > 0; o >>= 1) {
        s += __shfl_xor_sync(0xffffffffu, s, o);
        q += __shfl_xor_sync(0xffffffffu, q, o);
    }
    float mu = s * (1.f / DIM);
    float rsd = rsqrtf(q * (1.f / DIM) - mu * mu + LN_EPS);

    float4 ga = *(const float4*)&gamma[lane * 4];
    float4 be = *(const float4*)&beta[lane * 4];
    float4 y;
    y.x = (v.x - mu) * rsd * ga.x + be.x;
    y.y = (v.y - mu) * rsd * ga.y + be.y;
    y.z = (v.z - mu) * rsd * ga.z + be.z;
    y.w = (v.w - mu) * rsd * ga.w + be.w;
    y.x = y.x > 0.f ? y.x : (__expf(y.x) - 1.f);
    y.y = y.y > 0.f ? y.y : (__expf(y.y) - 1.f);
    y.z = y.z > 0.f ? y.z : (__expf(y.z) - 1.f);
    y.w = y.w > 0.f ? y.w : (__expf(y.w) - 1.f);
    *(float4*)&out[(size_t)i * DIM + lane * 4] = y;
}

// ---------------- launch ----------------------------------------------------
extern "C" void kernel_launch(void* const* d_in, const int* in_sizes, int n_in,
                              void* d_out, int out_size) {
    const float* x     = (const float*)d_in[0];
    const int*   ei    = (const int*)d_in[1];      // int64 in reference -> int32 in harness
    const float* W     = (const float*)d_in[2];
    const float* att_s = (const float*)d_in[3];
    const float* att_d = (const float*)d_in[4];
    const float* bias  = (const float*)d_in[5];
    const float* gamma = (const float*)d_in[6];
    const float* beta  = (const float*)d_in[7];
    float* out = (float*)d_out;

    const int N = in_sizes[0] / DIM;       // 100000
    const int E = in_sizes[1] / 2;         // 1600000

    static int smem_set = 0;
    if (!smem_set) {
        cudaFuncSetAttribute(k_gemm, cudaFuncAttributeMaxDynamicSharedMemorySize, SMEM_BYTES);
        smem_set = 1;
    }

    k_gemm <<<(N + 127) / 128, 256, SMEM_BYTES>>>(x, W, att_s, att_d, N);
    int warps = (E + EPW - 1) / EPW;
    k_acc  <<<(warps * 32 + 255) / 256, 256>>>(ei, E);
    k_final<<<(N * 32 + 255) / 256, 256>>>(bias, gamma, beta, out, N);
}